// round 9
// baseline (speedup 1.0000x reference)
#include <cuda_runtime.h>
#include <cuda_fp16.h>
#include <cstdint>

#define N_NODES 100000
#define N_PAIRS 160000
#define N_EDGES 320000
#define HIDDEN  256
#define DEPTH   3

// ---------------- scratch (device globals; no runtime allocation) ----------------
__device__ float  g_H[(size_t)N_EDGES * HIDDEN];
__device__ float  g_Mv[(size_t)N_NODES * HIDDEN];
__device__ __half g_Wh[(size_t)DEPTH * HIDDEN * HIDDEN];
__device__ int    g_counts[N_NODES];   // zero at load; re-zeroed by final segsum
__device__ int    g_offs[N_NODES + 1];
__device__ int    g_cursor[N_NODES];
__device__ int    g_elist[N_EDGES];
__device__ int    g_bincl[128];
__device__ int    g_bflag[128];        // zero at load; re-zeroed by final segsum
__device__ int    g_done;              // zero at load; re-zeroed by final segsum

__device__ __forceinline__ int rev_of(int e) {
    int r = e + N_PAIRS;
    return (r >= N_EDGES) ? r - N_EDGES : r;
}

// ---------------- launch 0: H0 init + histogram + W->fp16 (merged) ----------------
__global__ void k_inithist(const float* __restrict__ V, const float* __restrict__ E,
                           const int* __restrict__ src, const float* __restrict__ W) {
    int b = blockIdx.x;
    if (b < 80000) {
        int i = b * 256 + threadIdx.x;      // over N_EDGES*64 float4s
        int e = i >> 6, c = i & 63;
        int s = src[e];
        float4 ev = ((const float4*)E)[(size_t)e * 64 + c];
        float4 vv = ((const float4*)V)[(size_t)s * 64 + c];
        float4 o;
        o.x = ev.x + vv.x; o.y = ev.y + vv.y; o.z = ev.z + vv.z; o.w = ev.w + vv.w;
        ((float4*)g_H)[(size_t)e * 64 + c] = o;
    } else if (b < 81250) {
        int e = (b - 80000) * 256 + threadIdx.x;
        if (e < N_EDGES) atomicAdd(&g_counts[src[e]], 1);
    } else {
        int i = (b - 81250) * 256 + threadIdx.x;
        if (i < DEPTH * HIDDEN * HIDDEN / 4) {
            float4 w = ((const float4*)W)[i];
            __half2 p0 = __floats2half2_rn(w.x, w.y);
            __half2 p1 = __floats2half2_rn(w.z, w.w);
            *(__half2*)(g_Wh + (size_t)i * 4)     = p0;
            *(__half2*)(g_Wh + (size_t)i * 4 + 2) = p1;
        }
    }
}

// ---------------- launch 1: scan + grid barrier + fill (98 co-resident blocks) ----------------
__global__ void k_scanfill(const int* __restrict__ src) {
    __shared__ int s_wsum[32];
    __shared__ int s_prev;
    const int b = blockIdx.x;
    const int nb = gridDim.x;
    int i = b * 1024 + threadIdx.x;
    int v = (i < N_NODES) ? g_counts[i] : 0;
    int lane = threadIdx.x & 31, w = threadIdx.x >> 5;
    int sc = v;
    #pragma unroll
    for (int d = 1; d < 32; d <<= 1) {
        int t = __shfl_up_sync(0xffffffffu, sc, d);
        if (lane >= d) sc += t;
    }
    if (lane == 31) s_wsum[w] = sc;
    __syncthreads();
    if (w == 0) {
        int ws = s_wsum[lane];
        #pragma unroll
        for (int d = 1; d < 32; d <<= 1) {
            int t = __shfl_up_sync(0xffffffffu, ws, d);
            if (lane >= d) ws += t;
        }
        s_wsum[lane] = ws;
    }
    __syncthreads();
    int total = s_wsum[31];
    if (threadIdx.x == 0) {
        int prev = 0;
        if (b > 0) {
            while (atomicAdd(&g_bflag[b - 1], 0) == 0) {}
            prev = g_bincl[b - 1];
        }
        s_prev = prev;
        g_bincl[b] = prev + total;
        __threadfence();
        atomicExch(&g_bflag[b], 1);
        if (b == nb - 1) g_offs[N_NODES] = prev + total;
    }
    __syncthreads();
    int excl = sc - v + (w > 0 ? s_wsum[w - 1] : 0) + s_prev;
    if (i < N_NODES) {
        g_offs[i] = excl;
        g_cursor[i] = excl;
    }
    __syncthreads();
    if (threadIdx.x == 0) {
        __threadfence();
        atomicAdd(&g_done, 1);
        while (atomicAdd(&g_done, 0) < nb) {}
    }
    __syncthreads();
    for (int e = b * 1024 + threadIdx.x; e < N_EDGES; e += nb * 1024) {
        int pos = atomicAdd(&g_cursor[src[e]], 1);
        g_elist[pos] = e;
    }
}

// ---------------- segment sums via CSR: warp-per-node, edge loop unrolled x2 ----------------
template <bool RELU_REV>
__global__ void __launch_bounds__(256)
k_segsum(const float* __restrict__ H, float* __restrict__ out) {
    const int lane = threadIdx.x & 31;
    const int n = blockIdx.x * 8 + (threadIdx.x >> 5);
    if (!RELU_REV) {   // cleanup for next graph replay
        int gid = blockIdx.x * 256 + threadIdx.x;
        if (gid < N_NODES) g_counts[gid] = 0;
        if (gid < 128) g_bflag[gid] = 0;
        if (gid == 0) g_done = 0;
    }
    if (n >= N_NODES) return;
    const int beg = g_offs[n], end = g_offs[n + 1];
    float4 a0 = make_float4(0.f, 0.f, 0.f, 0.f);
    float4 a1 = make_float4(0.f, 0.f, 0.f, 0.f);
    int p = beg;
    for (; p + 2 <= end; p += 2) {
        int ea = g_elist[p], eb = g_elist[p + 1];
        if (RELU_REV) { ea = rev_of(ea); eb = rev_of(eb); }
        float4 x0 = ((const float4*)H)[(size_t)ea * 64 + lane];
        float4 x1 = ((const float4*)H)[(size_t)ea * 64 + lane + 32];
        float4 y0 = ((const float4*)H)[(size_t)eb * 64 + lane];
        float4 y1 = ((const float4*)H)[(size_t)eb * 64 + lane + 32];
        if (RELU_REV) {
            x0.x = fmaxf(x0.x, 0.f); x0.y = fmaxf(x0.y, 0.f); x0.z = fmaxf(x0.z, 0.f); x0.w = fmaxf(x0.w, 0.f);
            x1.x = fmaxf(x1.x, 0.f); x1.y = fmaxf(x1.y, 0.f); x1.z = fmaxf(x1.z, 0.f); x1.w = fmaxf(x1.w, 0.f);
            y0.x = fmaxf(y0.x, 0.f); y0.y = fmaxf(y0.y, 0.f); y0.z = fmaxf(y0.z, 0.f); y0.w = fmaxf(y0.w, 0.f);
            y1.x = fmaxf(y1.x, 0.f); y1.y = fmaxf(y1.y, 0.f); y1.z = fmaxf(y1.z, 0.f); y1.w = fmaxf(y1.w, 0.f);
        }
        a0.x += x0.x + y0.x; a0.y += x0.y + y0.y; a0.z += x0.z + y0.z; a0.w += x0.w + y0.w;
        a1.x += x1.x + y1.x; a1.y += x1.y + y1.y; a1.z += x1.z + y1.z; a1.w += x1.w + y1.w;
    }
    if (p < end) {
        int ea = g_elist[p];
        if (RELU_REV) ea = rev_of(ea);
        float4 x0 = ((const float4*)H)[(size_t)ea * 64 + lane];
        float4 x1 = ((const float4*)H)[(size_t)ea * 64 + lane + 32];
        if (RELU_REV) {
            x0.x = fmaxf(x0.x, 0.f); x0.y = fmaxf(x0.y, 0.f); x0.z = fmaxf(x0.z, 0.f); x0.w = fmaxf(x0.w, 0.f);
            x1.x = fmaxf(x1.x, 0.f); x1.y = fmaxf(x1.y, 0.f); x1.z = fmaxf(x1.z, 0.f); x1.w = fmaxf(x1.w, 0.f);
        }
        a0.x += x0.x; a0.y += x0.y; a0.z += x0.z; a0.w += x0.w;
        a1.x += x1.x; a1.y += x1.y; a1.z += x1.z; a1.w += x1.w;
    }
    ((float4*)out)[(size_t)n * 64 + lane] = a0;
    ((float4*)out)[(size_t)n * 64 + lane + 32] = a1;
}

// ---------------- fused fp16 GEMM: 64x128 tiles, 3 CTAs/SM ----------------
// Grid (5000, 2): blockIdx.x = row tile j (edges [32j,+32) U [160000+32j,+32)),
// blockIdx.y = ch = column half (cols [128ch, 128ch+128)).
//   A[i,k] = fp16( sMv[i,k] - relu(sH[i^32,k]) );  residual sH folded into acc
//   when chunk kt covers this CTA's columns;  H_out = acc + b.
// 8 warps, warp tile 32x32.  Rings: B/H/Mv 5-deep cp.async (distance 4); A 2-deep.
// A/B smem rows are 32B with XOR chunk swizzle (c ^= (row>>2)&1): conflict-free
// STS + ldmatrix.  Smem 64KB/CTA -> 3 CTAs/SM; launch_bounds(256,3) caps regs.

#define BM 64
#define BK 16
#define NST 5
#define A_SLOTB 2048                       // 64 rows x 32B
#define B_SLOTB 4096                       // 128 rows x 32B
#define H_SLOTB 4096                       // 64 rows x 64B
#define OFF_A 0
#define OFF_B (2 * A_SLOTB)                // 4096
#define OFF_H (OFF_B + NST * B_SLOTB)      // 24576
#define OFF_MV (OFF_H + NST * H_SLOTB)     // 45056
#define GEMM_SMEM (OFF_MV + NST * H_SLOTB) // 65536

#define LDSM_X4(r0, r1, r2, r3, addr) \
    asm volatile("ldmatrix.sync.aligned.m8n8.x4.shared.b16 {%0,%1,%2,%3}, [%4];" \
        : "=r"(r0), "=r"(r1), "=r"(r2), "=r"(r3) : "r"(addr))

__device__ __forceinline__ void mma_f16(float* d, const unsigned* a, const unsigned* b) {
    asm volatile(
        "mma.sync.aligned.m16n8k16.row.col.f32.f16.f16.f32 "
        "{%0,%1,%2,%3}, {%4,%5,%6,%7}, {%8,%9}, {%0,%1,%2,%3};\n"
        : "+f"(d[0]), "+f"(d[1]), "+f"(d[2]), "+f"(d[3])
        : "r"(a[0]), "r"(a[1]), "r"(a[2]), "r"(a[3]), "r"(b[0]), "r"(b[1]));
}

__global__ void __launch_bounds__(256, 3)
k_gemm(const float* __restrict__ Hin, const float* __restrict__ Mv,
       const int* __restrict__ src, const __half* __restrict__ Wl,
       const float* __restrict__ bl, float* __restrict__ Hout) {
    extern __shared__ char smc[];
    const uint32_t sbase = (uint32_t)__cvta_generic_to_shared(smc);

    const int t = threadIdx.x;
    const int j = blockIdx.x;
    const int ch = blockIdx.y;          // column half
    const int e1 = j * 32;
    const int e2 = N_PAIRS + j * 32;

    const int lane = t & 31, wid = t >> 5;
    const int wm = wid >> 2, wn = wid & 3;
    const int lr = lane >> 2, lc = lane & 3;

    float acc[2][4][4];
    #pragma unroll
    for (int mi = 0; mi < 2; ++mi)
        #pragma unroll
        for (int ni = 0; ni < 4; ++ni)
            #pragma unroll
            for (int q = 0; q < 4; ++q) acc[mi][ni][q] = 0.f;

    // producers: thread t -> row t>>2, 16B at float-cols (t&3)*4 of each chunk
    const int arow = t >> 2;
    const int ac4 = (t & 3) * 4;
    const int aedge = (arow < 32) ? (e1 + arow) : (e2 + arow - 32);
    const float* mp = Mv + (size_t)src[aedge] * HIDDEN + ac4;
    const float* hgp = Hin + (size_t)aedge * HIDDEN + ac4;

    // A store address (8B per thread, swizzled 32B rows)
    const uint32_t aSt = sbase + OFF_A
        + (uint32_t)(arow * 32 + (((ac4 >> 3) ^ ((arow >> 2) & 1)) << 4) + ((ac4 & 4) << 1));

    // B store: thread t -> row n = t>>1, chunk c = t&1 (swizzled)
    const int bn = t >> 1, bc = t & 1;
    const uint32_t bSt = sbase + OFF_B
        + (uint32_t)(bn * 32 + ((bc ^ ((bn >> 2) & 1)) << 4));
    const __half* wp = Wl + (size_t)(ch * 128 + bn) * HIDDEN + bc * 8;

    // ldmatrix lane addresses
    const int tsel = lane >> 3, lrow2 = lane & 7;
    const int arw = wm * 32 + (tsel & 1) * 8 + lrow2;
    const uint32_t aLd = sbase + OFF_A
        + (uint32_t)(arw * 32 + (((tsel >> 1) ^ ((arw >> 2) & 1)) << 4));
    uint32_t bLd[2];
    #pragma unroll
    for (int p = 0; p < 2; ++p) {
        const int brw = wn * 32 + p * 16 + (tsel >> 1) * 8 + lrow2;
        bLd[p] = sbase + OFF_B
            + (uint32_t)(brw * 32 + (((tsel & 1) ^ ((brw >> 2) & 1)) << 4));
    }

    auto issue = [&](int kt) {
        const int slot = kt % NST;
        const int k0 = kt * BK;
        {   // B: 128 rows x 32B, 1 x 16B / thread
            asm volatile("cp.async.cg.shared.global [%0], [%1], 16;\n"
                :: "r"(bSt + slot * B_SLOTB), "l"(wp + k0));
        }
        {   // Hin: 1 x 16B / thread
            uint32_t dst = sbase + OFF_H + slot * H_SLOTB + arow * 64 + ac4 * 4;
            asm volatile("cp.async.cg.shared.global [%0], [%1], 16;\n" :: "r"(dst), "l"(hgp + k0));
        }
        {   // Mv: 1 x 16B / thread (gathered)
            uint32_t dst = sbase + OFF_MV + slot * H_SLOTB + arow * 64 + ac4 * 4;
            asm volatile("cp.async.cg.shared.global [%0], [%1], 16;\n" :: "r"(dst), "l"(mp + k0));
        }
        asm volatile("cp.async.commit_group;\n");
    };

    auto storeA = [&](int kt) {
        const int slot = kt % NST;
        const float4 m = *(const float4*)(smc + OFF_MV + slot * H_SLOTB + arow * 64 + ac4 * 4);
        const float4 h = *(const float4*)(smc + OFF_H + slot * H_SLOTB + (arow ^ 32) * 64 + ac4 * 4);
        __half2 p0 = __floats2half2_rn(m.x - fmaxf(h.x, 0.f), m.y - fmaxf(h.y, 0.f));
        __half2 p1 = __floats2half2_rn(m.z - fmaxf(h.z, 0.f), m.w - fmaxf(h.w, 0.f));
        char* pa = (char*)smc + (aSt - sbase) + (kt & 1) * A_SLOTB;
        *(__half2*)(pa) = p0;
        *(__half2*)(pa + 4) = p1;
    };

    const int KT = HIDDEN / BK;  // 16

    issue(0); issue(1); issue(2); issue(3);
    asm volatile("cp.async.wait_group 3;\n");
    __syncthreads();
    storeA(0);

    #pragma unroll
    for (int kt = 0; kt < KT; ++kt) {
        if (kt <= 12)      asm volatile("cp.async.wait_group 2;\n");
        else if (kt == 13) asm volatile("cp.async.wait_group 1;\n");
        else               asm volatile("cp.async.wait_group 0;\n");
        __syncthreads();

        if (kt + 1 < KT) storeA(kt + 1);

        const int slot = kt % NST;

        // residual: chunk kt covers global cols [16kt,+16) -> ours iff (kt>>3)==ch
        if ((kt >> 3) == ch && wn == ((kt & 7) >> 1)) {
            const int kl = kt & 7;
            const float* h0 = (const float*)(smc + OFF_H + slot * H_SLOTB) + (wm * 32) * 16;
            #pragma unroll
            for (int mi = 0; mi < 2; ++mi) {
                #pragma unroll
                for (int q = 0; q < 2; ++q) {
                    const int ni = (kl & 1) * 2 + q;
                    const float* hp2 = h0 + (mi * 16 + lr) * 16 + q * 8 + lc * 2;
                    float2 v0 = *(const float2*)hp2;
                    float2 v1 = *(const float2*)(hp2 + 8 * 16);
                    acc[mi][ni][0] += v0.x; acc[mi][ni][1] += v0.y;
                    acc[mi][ni][2] += v1.x; acc[mi][ni][3] += v1.y;
                }
            }
        }

        // fragments via ldmatrix (A slot = kt&1, written last iteration)
        unsigned af[2][4], bf[2][4];
        {
            const uint32_t aS = aLd + (kt & 1) * A_SLOTB;
            LDSM_X4(af[0][0], af[0][1], af[0][2], af[0][3], aS);
            LDSM_X4(af[1][0], af[1][1], af[1][2], af[1][3], aS + 16 * 32);
        }
        #pragma unroll
        for (int p = 0; p < 2; ++p)
            LDSM_X4(bf[p][0], bf[p][1], bf[p][2], bf[p][3], bLd[p] + slot * B_SLOTB);
        #pragma unroll
        for (int mi = 0; mi < 2; ++mi) {
            #pragma unroll
            for (int p = 0; p < 2; ++p) {
                mma_f16(acc[mi][2 * p],     af[mi], &bf[p][0]);
                mma_f16(acc[mi][2 * p + 1], af[mi], &bf[p][2]);
            }
        }

        if (kt + 4 < KT) issue(kt + 4);
    }

    // epilogue: H_out = acc + b (residual already folded)
    float2 bb[4];
    #pragma unroll
    for (int ni = 0; ni < 4; ++ni)
        bb[ni] = *(const float2*)(bl + ch * 128 + wn * 32 + ni * 8 + lc * 2);

    #pragma unroll
    for (int mi = 0; mi < 2; ++mi) {
        const int r0 = wm * 32 + mi * 16 + lr;
        const int r1 = r0 + 8;
        const int ge0 = (r0 < 32) ? (e1 + r0) : (e2 + r0 - 32);
        const int ge1 = (r1 < 32) ? (e1 + r1) : (e2 + r1 - 32);
        #pragma unroll
        for (int ni = 0; ni < 4; ++ni) {
            int c0 = ch * 128 + wn * 32 + ni * 8 + lc * 2;
            float2 o0, o1;
            o0.x = bb[ni].x + acc[mi][ni][0];
            o0.y = bb[ni].y + acc[mi][ni][1];
            o1.x = bb[ni].x + acc[mi][ni][2];
            o1.y = bb[ni].y + acc[mi][ni][3];
            *(float2*)(Hout + (size_t)ge0 * HIDDEN + c0) = o0;
            *(float2*)(Hout + (size_t)ge1 * HIDDEN + c0) = o1;
        }
    }
}

// ---------------- launch ----------------
extern "C" void kernel_launch(void* const* d_in, const int* in_sizes, int n_in,
                              void* d_out, int out_size) {
    const float* V = (const float*)d_in[0];
    const float* E = (const float*)d_in[1];
    const float* W = (const float*)d_in[2];
    const float* b = (const float*)d_in[3];
    const int* edge_index = (const int*)d_in[4];
    const int* src = edge_index;

    float* outV = (float*)d_out;
    float* outH = outV + (size_t)N_NODES * HIDDEN;

    float* gH = nullptr;
    float* gMv = nullptr;
    __half* gWh = nullptr;
    cudaGetSymbolAddress((void**)&gH, g_H);
    cudaGetSymbolAddress((void**)&gMv, g_Mv);
    cudaGetSymbolAddress((void**)&gWh, g_Wh);

    cudaFuncSetAttribute(k_gemm, cudaFuncAttributeMaxDynamicSharedMemorySize, GEMM_SMEM);

    // launches: inithist(0), scanfill(1), segsum(2), gemm(3) <- ncu captures idx 3
    k_inithist<<<81442, 256>>>(V, E, src, W);
    k_scanfill<<<98, 1024>>>(src);

    float* bufs[2] = {gH, outH};
    for (int l = 0; l < DEPTH; ++l) {
        const float* Hin = bufs[l & 1];
        float* Hout = bufs[(l + 1) & 1];
        k_segsum<true><<<12500, 256>>>(Hin, gMv);
        k_gemm<<<dim3(N_EDGES / BM, 2), 256, GEMM_SMEM>>>(Hin, gMv, src,
                                                 gWh + (size_t)l * HIDDEN * HIDDEN,
                                                 b + (size_t)l * HIDDEN, Hout);
    }
    k_segsum<false><<<12500, 256>>>(outH, outV);
}

// round 10
// speedup vs baseline: 1.1445x; 1.1445x over previous
#include <cuda_runtime.h>
#include <cuda_fp16.h>
#include <cstdint>

#define N_NODES 100000
#define N_PAIRS 160000
#define N_EDGES 320000
#define HIDDEN  256
#define DEPTH   3

// ---------------- scratch (device globals; no runtime allocation) ----------------
__device__ float  g_H[(size_t)N_EDGES * HIDDEN];
__device__ float  g_Mv[(size_t)N_NODES * HIDDEN];
__device__ __half g_Wh[(size_t)DEPTH * HIDDEN * HIDDEN];
__device__ int    g_counts[N_NODES];   // zero at load; re-zeroed by final segsum
__device__ int    g_offs[N_NODES + 1];
__device__ int    g_cursor[N_NODES];
__device__ int    g_elist[N_EDGES];
__device__ int    g_bincl[128];
__device__ int    g_bflag[128];        // zero at load; re-zeroed by final segsum
__device__ int    g_done;              // zero at load; re-zeroed by final segsum

__device__ __forceinline__ int rev_of(int e) {
    int r = e + N_PAIRS;
    return (r >= N_EDGES) ? r - N_EDGES : r;
}

// ---------------- launch 0: H0 init + histogram + W->fp16 (merged) ----------------
__global__ void k_inithist(const float* __restrict__ V, const float* __restrict__ E,
                           const int* __restrict__ src, const float* __restrict__ W) {
    int b = blockIdx.x;
    if (b < 80000) {
        int i = b * 256 + threadIdx.x;      // over N_EDGES*64 float4s
        int e = i >> 6, c = i & 63;
        int s = src[e];
        float4 ev = __ldcs(&((const float4*)E)[(size_t)e * 64 + c]);
        float4 vv = ((const float4*)V)[(size_t)s * 64 + c];
        float4 o;
        o.x = ev.x + vv.x; o.y = ev.y + vv.y; o.z = ev.z + vv.z; o.w = ev.w + vv.w;
        __stcs(&((float4*)g_H)[(size_t)e * 64 + c], o);
    } else if (b < 81250) {
        int e = (b - 80000) * 256 + threadIdx.x;
        if (e < N_EDGES) atomicAdd(&g_counts[src[e]], 1);
    } else {
        int i = (b - 81250) * 256 + threadIdx.x;
        if (i < DEPTH * HIDDEN * HIDDEN / 4) {
            float4 w = ((const float4*)W)[i];
            __half2 p0 = __floats2half2_rn(w.x, w.y);
            __half2 p1 = __floats2half2_rn(w.z, w.w);
            *(__half2*)(g_Wh + (size_t)i * 4)     = p0;
            *(__half2*)(g_Wh + (size_t)i * 4 + 2) = p1;
        }
    }
}

// ---------------- launch 1: scan + grid barrier + fill (98 co-resident blocks) ----------------
__global__ void k_scanfill(const int* __restrict__ src) {
    __shared__ int s_wsum[32];
    __shared__ int s_prev;
    const int b = blockIdx.x;
    const int nb = gridDim.x;
    int i = b * 1024 + threadIdx.x;
    int v = (i < N_NODES) ? g_counts[i] : 0;
    int lane = threadIdx.x & 31, w = threadIdx.x >> 5;
    int sc = v;
    #pragma unroll
    for (int d = 1; d < 32; d <<= 1) {
        int t = __shfl_up_sync(0xffffffffu, sc, d);
        if (lane >= d) sc += t;
    }
    if (lane == 31) s_wsum[w] = sc;
    __syncthreads();
    if (w == 0) {
        int ws = s_wsum[lane];
        #pragma unroll
        for (int d = 1; d < 32; d <<= 1) {
            int t = __shfl_up_sync(0xffffffffu, ws, d);
            if (lane >= d) ws += t;
        }
        s_wsum[lane] = ws;
    }
    __syncthreads();
    int total = s_wsum[31];
    if (threadIdx.x == 0) {
        int prev = 0;
        if (b > 0) {
            while (atomicAdd(&g_bflag[b - 1], 0) == 0) {}
            prev = g_bincl[b - 1];
        }
        s_prev = prev;
        g_bincl[b] = prev + total;
        __threadfence();
        atomicExch(&g_bflag[b], 1);
        if (b == nb - 1) g_offs[N_NODES] = prev + total;
    }
    __syncthreads();
    int excl = sc - v + (w > 0 ? s_wsum[w - 1] : 0) + s_prev;
    if (i < N_NODES) {
        g_offs[i] = excl;
        g_cursor[i] = excl;
    }
    __syncthreads();
    if (threadIdx.x == 0) {
        __threadfence();
        atomicAdd(&g_done, 1);
        while (atomicAdd(&g_done, 0) < nb) {}
    }
    __syncthreads();
    for (int e = b * 1024 + threadIdx.x; e < N_EDGES; e += nb * 1024) {
        int pos = atomicAdd(&g_cursor[src[e]], 1);
        g_elist[pos] = e;
    }
}

// ---------------- segment sums via CSR: warp-per-node, edge loop unrolled x2 ----------------
template <bool RELU_REV>
__global__ void __launch_bounds__(256)
k_segsum(const float* __restrict__ H, float* __restrict__ out) {
    const int lane = threadIdx.x & 31;
    const int n = blockIdx.x * 8 + (threadIdx.x >> 5);
    if (!RELU_REV) {   // cleanup for next graph replay
        int gid = blockIdx.x * 256 + threadIdx.x;
        if (gid < N_NODES) g_counts[gid] = 0;
        if (gid < 128) g_bflag[gid] = 0;
        if (gid == 0) g_done = 0;
    }
    if (n >= N_NODES) return;
    const int beg = g_offs[n], end = g_offs[n + 1];
    float4 a0 = make_float4(0.f, 0.f, 0.f, 0.f);
    float4 a1 = make_float4(0.f, 0.f, 0.f, 0.f);
    int p = beg;
    for (; p + 2 <= end; p += 2) {
        int ea = g_elist[p], eb = g_elist[p + 1];
        if (RELU_REV) { ea = rev_of(ea); eb = rev_of(eb); }
        float4 x0 = __ldcs(&((const float4*)H)[(size_t)ea * 64 + lane]);
        float4 x1 = __ldcs(&((const float4*)H)[(size_t)ea * 64 + lane + 32]);
        float4 y0 = __ldcs(&((const float4*)H)[(size_t)eb * 64 + lane]);
        float4 y1 = __ldcs(&((const float4*)H)[(size_t)eb * 64 + lane + 32]);
        if (RELU_REV) {
            x0.x = fmaxf(x0.x, 0.f); x0.y = fmaxf(x0.y, 0.f); x0.z = fmaxf(x0.z, 0.f); x0.w = fmaxf(x0.w, 0.f);
            x1.x = fmaxf(x1.x, 0.f); x1.y = fmaxf(x1.y, 0.f); x1.z = fmaxf(x1.z, 0.f); x1.w = fmaxf(x1.w, 0.f);
            y0.x = fmaxf(y0.x, 0.f); y0.y = fmaxf(y0.y, 0.f); y0.z = fmaxf(y0.z, 0.f); y0.w = fmaxf(y0.w, 0.f);
            y1.x = fmaxf(y1.x, 0.f); y1.y = fmaxf(y1.y, 0.f); y1.z = fmaxf(y1.z, 0.f); y1.w = fmaxf(y1.w, 0.f);
        }
        a0.x += x0.x + y0.x; a0.y += x0.y + y0.y; a0.z += x0.z + y0.z; a0.w += x0.w + y0.w;
        a1.x += x1.x + y1.x; a1.y += x1.y + y1.y; a1.z += x1.z + y1.z; a1.w += x1.w + y1.w;
    }
    if (p < end) {
        int ea = g_elist[p];
        if (RELU_REV) ea = rev_of(ea);
        float4 x0 = __ldcs(&((const float4*)H)[(size_t)ea * 64 + lane]);
        float4 x1 = __ldcs(&((const float4*)H)[(size_t)ea * 64 + lane + 32]);
        if (RELU_REV) {
            x0.x = fmaxf(x0.x, 0.f); x0.y = fmaxf(x0.y, 0.f); x0.z = fmaxf(x0.z, 0.f); x0.w = fmaxf(x0.w, 0.f);
            x1.x = fmaxf(x1.x, 0.f); x1.y = fmaxf(x1.y, 0.f); x1.z = fmaxf(x1.z, 0.f); x1.w = fmaxf(x1.w, 0.f);
        }
        a0.x += x0.x; a0.y += x0.y; a0.z += x0.z; a0.w += x0.w;
        a1.x += x1.x; a1.y += x1.y; a1.z += x1.z; a1.w += x1.w;
    }
    ((float4*)out)[(size_t)n * 64 + lane] = a0;
    ((float4*)out)[(size_t)n * 64 + lane + 32] = a1;
}

// ---------------- fused fp16 GEMM: R8 geometry + 6-deep rings + L2 hints ----------------
// Tile j rows: edges [32j,32j+32) U [160000+32j,+32); rev maps tile onto itself (row^32).
//   A[i,k] = fp16( sMv[i,k] - relu(sH[i^32,k]) );  residual sH folded into acc;
//   H_out = acc + b.  Block 64x256, 8 warps (2x4), warp tile 32x64, 2 CTAs/SM.
// Rings: B/H/Mv 6-deep cp.async (issue distance 5, wait_group 3); A 2-deep.
// A/B smem: 32B rows, XOR chunk swizzle (c ^= (row>>2)&1) — conflict-free STS+ldmatrix.
// L2: Hin evict_first (stream), Mv evict_last (keep resident), Hout __stcs.

#define BM 64
#define BK 16
#define NST 6
#define A_SLOTB 2048                       // 64 rows x 32B
#define B_SLOTB 8192                       // 256 rows x 32B
#define H_SLOTB 4096                       // 64 rows x 64B
#define OFF_A 0
#define OFF_B (2 * A_SLOTB)                // 4096
#define OFF_H (OFF_B + NST * B_SLOTB)      // 53248
#define OFF_MV (OFF_H + NST * H_SLOTB)     // 77824
#define GEMM_SMEM (OFF_MV + NST * H_SLOTB) // 102400

#define LDSM_X4(r0, r1, r2, r3, addr) \
    asm volatile("ldmatrix.sync.aligned.m8n8.x4.shared.b16 {%0,%1,%2,%3}, [%4];" \
        : "=r"(r0), "=r"(r1), "=r"(r2), "=r"(r3) : "r"(addr))

__device__ __forceinline__ void mma_f16(float* d, const unsigned* a, const unsigned* b) {
    asm volatile(
        "mma.sync.aligned.m16n8k16.row.col.f32.f16.f16.f32 "
        "{%0,%1,%2,%3}, {%4,%5,%6,%7}, {%8,%9}, {%0,%1,%2,%3};\n"
        : "+f"(d[0]), "+f"(d[1]), "+f"(d[2]), "+f"(d[3])
        : "r"(a[0]), "r"(a[1]), "r"(a[2]), "r"(a[3]), "r"(b[0]), "r"(b[1]));
}

__global__ void __launch_bounds__(256, 2)
k_gemm(const float* __restrict__ Hin, const float* __restrict__ Mv,
       const int* __restrict__ src, const __half* __restrict__ Wl,
       const float* __restrict__ bl, float* __restrict__ Hout) {
    extern __shared__ char smc[];
    const uint32_t sbase = (uint32_t)__cvta_generic_to_shared(smc);

    const int t = threadIdx.x;
    const int j = blockIdx.x;
    const int e1 = j * 32;
    const int e2 = N_PAIRS + j * 32;

    const int lane = t & 31, wid = t >> 5;
    const int wm = wid >> 2, wn = wid & 3;
    const int lr = lane >> 2, lc = lane & 3;

    uint64_t polF, polL;   // L2 policies: stream Hin, keep Mv
    asm("createpolicy.fractional.L2::evict_first.b64 %0, 1.0;" : "=l"(polF));
    asm("createpolicy.fractional.L2::evict_last.b64 %0, 1.0;" : "=l"(polL));

    float acc[2][8][4];
    #pragma unroll
    for (int mi = 0; mi < 2; ++mi)
        #pragma unroll
        for (int ni = 0; ni < 8; ++ni)
            #pragma unroll
            for (int q = 0; q < 4; ++q) acc[mi][ni][q] = 0.f;

    // producers: thread t -> row t>>2, 16B at float-cols (t&3)*4 of each chunk
    const int arow = t >> 2;
    const int ac4 = (t & 3) * 4;
    const int aedge = (arow < 32) ? (e1 + arow) : (e2 + arow - 32);
    const float* mp = Mv + (size_t)src[aedge] * HIDDEN + ac4;
    const float* hgp = Hin + (size_t)aedge * HIDDEN + ac4;

    // A store: 8B/thread into swizzled 32B rows
    const uint32_t aSt = sbase + OFF_A
        + (uint32_t)(arow * 32 + (((ac4 >> 3) ^ ((arow >> 2) & 1)) << 4) + ((ac4 & 4) << 1));

    // B store: f = t + i*256 -> row n = f>>1, chunk c = f&1 (swizzled)
    // ldmatrix lane addresses (32B swizzled rows; +16-row offsets preserve parity)
    const int tsel = lane >> 3, lrow2 = lane & 7;
    const int arw = wm * 32 + (tsel & 1) * 8 + lrow2;
    const uint32_t aLd = sbase + OFF_A
        + (uint32_t)(arw * 32 + (((tsel >> 1) ^ ((arw >> 2) & 1)) << 4));
    const int brw0 = wn * 64 + (tsel >> 1) * 8 + lrow2;
    const uint32_t bLd0 = sbase + OFF_B
        + (uint32_t)(brw0 * 32 + (((tsel & 1) ^ ((brw0 >> 2) & 1)) << 4));

    auto issue = [&](int kt) {
        const int slot = kt % NST;
        const int k0 = kt * BK;
        #pragma unroll
        for (int i = 0; i < 2; ++i) {   // B: 512 16B copies, 2/thread
            int f = t + i * 256;
            int n = f >> 1, c = f & 1;
            uint32_t dst = sbase + OFF_B + slot * B_SLOTB
                + (uint32_t)(n * 32 + ((c ^ ((n >> 2) & 1)) << 4));
            const __half* sp = Wl + (size_t)n * HIDDEN + k0 + c * 8;
            asm volatile("cp.async.cg.shared.global [%0], [%1], 16;\n" :: "r"(dst), "l"(sp));
        }
        {   // Hin: 1 x 16B / thread, streaming (evict_first)
            uint32_t dst = sbase + OFF_H + slot * H_SLOTB + arow * 64 + ac4 * 4;
            asm volatile("cp.async.cg.shared.global.L2::cache_hint [%0], [%1], 16, %2;\n"
                :: "r"(dst), "l"(hgp + k0), "l"(polF));
        }
        {   // Mv: 1 x 16B / thread (gathered), keep resident (evict_last)
            uint32_t dst = sbase + OFF_MV + slot * H_SLOTB + arow * 64 + ac4 * 4;
            asm volatile("cp.async.cg.shared.global.L2::cache_hint [%0], [%1], 16, %2;\n"
                :: "r"(dst), "l"(mp + k0), "l"(polL));
        }
        asm volatile("cp.async.commit_group;\n");
    };

    auto storeA = [&](int kt) {
        const int slot = kt % NST;
        const float4 m = *(const float4*)(smc + OFF_MV + slot * H_SLOTB + arow * 64 + ac4 * 4);
        const float4 h = *(const float4*)(smc + OFF_H + slot * H_SLOTB + (arow ^ 32) * 64 + ac4 * 4);
        __half2 p0 = __floats2half2_rn(m.x - fmaxf(h.x, 0.f), m.y - fmaxf(h.y, 0.f));
        __half2 p1 = __floats2half2_rn(m.z - fmaxf(h.z, 0.f), m.w - fmaxf(h.w, 0.f));
        char* pa = (char*)smc + (aSt - sbase) + (kt & 1) * A_SLOTB;
        *(__half2*)(pa) = p0;
        *(__half2*)(pa + 4) = p1;
    };

    const int KT = HIDDEN / BK;  // 16

    issue(0); issue(1); issue(2); issue(3); issue(4);
    asm volatile("cp.async.wait_group 3;\n");
    __syncthreads();
    storeA(0);

    #pragma unroll
    for (int kt = 0; kt < KT; ++kt) {
        if (kt <= 11)      asm volatile("cp.async.wait_group 3;\n");
        else if (kt == 12) asm volatile("cp.async.wait_group 2;\n");
        else if (kt == 13) asm volatile("cp.async.wait_group 1;\n");
        else               asm volatile("cp.async.wait_group 0;\n");
        __syncthreads();

        if (kt + 1 < KT) storeA(kt + 1);

        const int slot = kt % NST;

        // residual: chunk kt holds cols [16kt,16kt+16) -> warp col wn == kt>>2
        if (wn == (kt >> 2)) {
            const float* h0 = (const float*)(smc + OFF_H + slot * H_SLOTB) + (wm * 32) * 16;
            #pragma unroll
            for (int mi = 0; mi < 2; ++mi) {
                #pragma unroll
                for (int q = 0; q < 2; ++q) {
                    const int ni = (kt & 3) * 2 + q;
                    const float* hp2 = h0 + (mi * 16 + lr) * 16 + q * 8 + lc * 2;
                    float2 v0 = *(const float2*)hp2;
                    float2 v1 = *(const float2*)(hp2 + 8 * 16);
                    acc[mi][ni][0] += v0.x; acc[mi][ni][1] += v0.y;
                    acc[mi][ni][2] += v1.x; acc[mi][ni][3] += v1.y;
                }
            }
        }

        // fragments via ldmatrix (A slot = kt&1, written last iteration)
        unsigned af[2][4], bf[4][4];
        {
            const uint32_t aS = aLd + (kt & 1) * A_SLOTB;
            LDSM_X4(af[0][0], af[0][1], af[0][2], af[0][3], aS);
            LDSM_X4(af[1][0], af[1][1], af[1][2], af[1][3], aS + 16 * 32);
        }
        {
            const uint32_t bS = bLd0 + slot * B_SLOTB;
            #pragma unroll
            for (int p = 0; p < 4; ++p)
                LDSM_X4(bf[p][0], bf[p][1], bf[p][2], bf[p][3], bS + p * 16 * 32);
        }
        #pragma unroll
        for (int mi = 0; mi < 2; ++mi) {
            #pragma unroll
            for (int p = 0; p < 4; ++p) {
                mma_f16(acc[mi][2 * p],     af[mi], &bf[p][0]);
                mma_f16(acc[mi][2 * p + 1], af[mi], &bf[p][2]);
            }
        }

        if (kt + 5 < KT) issue(kt + 5);
    }

    // epilogue: H_out = acc + b (residual already folded), streaming stores
    float2 bb[8];
    #pragma unroll
    for (int ni = 0; ni < 8; ++ni)
        bb[ni] = *(const float2*)(bl + wn * 64 + ni * 8 + lc * 2);

    #pragma unroll
    for (int mi = 0; mi < 2; ++mi) {
        const int r0 = wm * 32 + mi * 16 + lr;
        const int r1 = r0 + 8;
        const int ge0 = (r0 < 32) ? (e1 + r0) : (e2 + r0 - 32);
        const int ge1 = (r1 < 32) ? (e1 + r1) : (e2 + r1 - 32);
        #pragma unroll
        for (int ni = 0; ni < 8; ++ni) {
            int c0 = wn * 64 + ni * 8 + lc * 2;
            float2 o0, o1;
            o0.x = bb[ni].x + acc[mi][ni][0];
            o0.y = bb[ni].y + acc[mi][ni][1];
            o1.x = bb[ni].x + acc[mi][ni][2];
            o1.y = bb[ni].y + acc[mi][ni][3];
            __stcs((float2*)(Hout + (size_t)ge0 * HIDDEN + c0), o0);
            __stcs((float2*)(Hout + (size_t)ge1 * HIDDEN + c0), o1);
        }
    }
}

// ---------------- launch ----------------
extern "C" void kernel_launch(void* const* d_in, const int* in_sizes, int n_in,
                              void* d_out, int out_size) {
    const float* V = (const float*)d_in[0];
    const float* E = (const float*)d_in[1];
    const float* W = (const float*)d_in[2];
    const float* b = (const float*)d_in[3];
    const int* edge_index = (const int*)d_in[4];
    const int* src = edge_index;

    float* outV = (float*)d_out;
    float* outH = outV + (size_t)N_NODES * HIDDEN;

    float* gH = nullptr;
    float* gMv = nullptr;
    __half* gWh = nullptr;
    cudaGetSymbolAddress((void**)&gH, g_H);
    cudaGetSymbolAddress((void**)&gMv, g_Mv);
    cudaGetSymbolAddress((void**)&gWh, g_Wh);

    cudaFuncSetAttribute(k_gemm, cudaFuncAttributeMaxDynamicSharedMemorySize, GEMM_SMEM);

    // launches: inithist(0), scanfill(1), segsum(2), gemm(3) <- ncu captures idx 3
    k_inithist<<<81442, 256>>>(V, E, src, W);
    k_scanfill<<<98, 1024>>>(src);

    float* bufs[2] = {gH, outH};
    for (int l = 0; l < DEPTH; ++l) {
        const float* Hin = bufs[l & 1];
        float* Hout = bufs[(l + 1) & 1];
        k_segsum<true><<<12500, 256>>>(Hin, gMv);
        k_gemm<<<N_EDGES / BM, 256, GEMM_SMEM>>>(Hin, gMv, src,
                                                 gWh + (size_t)l * HIDDEN * HIDDEN,
                                                 b + (size_t)l * HIDDEN, Hout);
    }
    k_segsum<false><<<12500, 256>>>(outH, outV);
}